// round 8
// baseline (speedup 1.0000x reference)
#include <cuda_runtime.h>

#define IN_DIM   8192
#define OUT_DIM  16384
#define TOP_K    327

// scratch (no allocations allowed); zero-initialized at module load, and
// k_topk re-zeroes it at the end of every launch (graph-replay invariant).
__device__ int g_overlap[OUT_DIM];

// ---------------------------------------------------------------------------
// k_gemv: overlap[c] += sum over active rows of (p[row][c] > 0.5f)
//   grid = (COL_TILES=16, ROW_STRIPS=64), block = 256 threads.
//   Each block ballot-compacts its own 128-row strip of x (L2-resident),
//   then streams the active rows' 4KB column slices. launch_bounds(256,7)
//   guarantees 7 blocks/SM -> 1036 resident >= 1024 grid -> single wave.
// ---------------------------------------------------------------------------
#define GEMV_TB     256
#define STRIP       128                     // original rows per block
#define ROW_STRIPS  (IN_DIM / STRIP)        // 64
#define COLS_BLK    (GEMV_TB * 4)           // 1024
#define COL_TILES   (OUT_DIM / COLS_BLK)    // 16

__global__ __launch_bounds__(GEMV_TB, 7) void k_gemv(const int* __restrict__ x,
                                                     const float* __restrict__ p) {
    __shared__ int srows[STRIP];
    __shared__ int s_wcnt[4];

    const int t    = threadIdx.x;
    const int lane = t & 31;
    const int w    = t >> 5;
    const int r0   = blockIdx.y * STRIP;

    // --- local compaction of this block's 128-row strip (warps 0-3) ---
    int a = 0, myrow = 0;
    unsigned m = 0;
    if (w < 4) {
        myrow = r0 + t;
        a = (x[myrow] != 0);
        m = __ballot_sync(0xffffffffu, a);
        if (lane == 0) s_wcnt[w] = __popc(m);
    }
    __syncthreads();
    const int nr = s_wcnt[0] + s_wcnt[1] + s_wcnt[2] + s_wcnt[3];
    if (w < 4 && a) {
        int off = 0;
        #pragma unroll
        for (int i = 0; i < 4; i++) if (i < w) off += s_wcnt[i];
        int rank = __popc(m & ((1u << lane) - 1u));
        srows[off + rank] = myrow;
    }
    __syncthreads();
    if (nr == 0) return;

    // --- binarized accumulation over active rows (unroll 4, regs <= 36) ---
    const int col4 = blockIdx.x * (COLS_BLK / 4) + t;   // float4 index
    const float4* __restrict__ p4 = (const float4*)p;
    const long stride4 = OUT_DIM / 4;

    int c0 = 0, c1 = 0, c2 = 0, c3 = 0;

    int r = 0;
    #pragma unroll 1
    for (; r + 4 <= nr; r += 4) {
        #pragma unroll
        for (int u = 0; u < 4; u++) {
            const int row = srows[r + u];
            const float4 v = __ldg(&p4[(long)row * stride4 + col4]);
            c0 += (v.x > 0.5f);
            c1 += (v.y > 0.5f);
            c2 += (v.z > 0.5f);
            c3 += (v.w > 0.5f);
        }
    }
    for (; r < nr; r++) {
        const int row = srows[r];
        const float4 v = __ldg(&p4[(long)row * stride4 + col4]);
        c0 += (v.x > 0.5f);
        c1 += (v.y > 0.5f);
        c2 += (v.z > 0.5f);
        c3 += (v.w > 0.5f);
    }

    const int cbase = col4 * 4;
    atomicAdd(&g_overlap[cbase + 0], c0);
    atomicAdd(&g_overlap[cbase + 1], c1);
    atomicAdd(&g_overlap[cbase + 2], c2);
    atomicAdd(&g_overlap[cbase + 3], c3);
}

// ---------------------------------------------------------------------------
// k_topk: single block, 1024 threads. Register-resident binary search for the
// k-th largest value T, then jax.lax.top_k tie-break (lowest index wins).
// Epilogue re-zeroes g_overlap so the next graph replay starts clean.
// ---------------------------------------------------------------------------
#define TK_THREADS 1024
#define SEG        (OUT_DIM / TK_THREADS) // 16

__global__ __launch_bounds__(TK_THREADS) void k_topk(float* __restrict__ out) {
    __shared__ int s_warp[32];
    __shared__ int s_bc;

    const int t    = threadIdx.x;
    const int lane = t & 31;
    const int wid  = t >> 5;
    const int base = t * SEG;

    // load my 16 contiguous overlap values into registers (int4 vectorized)
    int ov[SEG];
    int4* g4 = (int4*)(g_overlap + base);
    #pragma unroll
    for (int j = 0; j < SEG / 4; j++) {
        int4 v = g4[j];
        ov[4 * j + 0] = v.x;
        ov[4 * j + 1] = v.y;
        ov[4 * j + 2] = v.z;
        ov[4 * j + 3] = v.w;
    }

    auto count_ge = [&](int m) -> int {
        int c = 0;
        #pragma unroll
        for (int j = 0; j < SEG; j++) c += (ov[j] >= m);
        #pragma unroll
        for (int o = 16; o; o >>= 1)
            c += __shfl_xor_sync(0xffffffffu, c, o);
        if (lane == 0) s_warp[wid] = c;
        __syncthreads();
        if (wid == 0) {
            int v = s_warp[lane];
            #pragma unroll
            for (int o = 16; o; o >>= 1)
                v += __shfl_xor_sync(0xffffffffu, v, o);
            if (lane == 0) s_bc = v;
        }
        __syncthreads();
        int r = s_bc;
        __syncthreads();
        return r;
    };

    // binary search: largest T with count(>= T) >= TOP_K
    int lo = 0, hi = IN_DIM;
    while (lo < hi) {
        int mid = (lo + hi + 1) >> 1;
        if (count_ge(mid) >= TOP_K) lo = mid;
        else                        hi = mid - 1;
    }
    const int T   = lo;
    const int rem = TOP_K - count_ge(T + 1);  // ties at T to accept (lowest index)

    // tie ranking: exclusive prefix of tie-counts in index order
    int cnt = 0;
    #pragma unroll
    for (int j = 0; j < SEG; j++) cnt += (ov[j] == T);

    int inc = cnt;
    #pragma unroll
    for (int o = 1; o < 32; o <<= 1) {
        int n = __shfl_up_sync(0xffffffffu, inc, o);
        if (lane >= o) inc += n;
    }
    if (lane == 31) s_warp[wid] = inc;
    __syncthreads();
    if (wid == 0) {
        int tot = s_warp[lane];
        int v = tot;
        #pragma unroll
        for (int o = 1; o < 32; o <<= 1) {
            int n = __shfl_up_sync(0xffffffffu, v, o);
            if (lane >= o) v += n;
        }
        s_warp[lane] = v - tot;
    }
    __syncthreads();
    int run = s_warp[wid] + (inc - cnt);

    // emit 0/1 output, float4 stores
    float4* o4 = (float4*)(out + base);
    #pragma unroll
    for (int j = 0; j < SEG / 4; j++) {
        float r[4];
        #pragma unroll
        for (int q = 0; q < 4; q++) {
            int v = ov[4 * j + q];
            float o;
            if (v > T) {
                o = 1.0f;
            } else if (v == T) {
                o = (run < rem) ? 1.0f : 0.0f;
                run++;
            } else {
                o = 0.0f;
            }
            r[q] = o;
        }
        o4[j] = make_float4(r[0], r[1], r[2], r[3]);
    }

    // reset accumulator for the next launch (all reads happened at kernel
    // start; every thread zeroes only its own segment)
    #pragma unroll
    for (int j = 0; j < SEG / 4; j++)
        g4[j] = make_int4(0, 0, 0, 0);
}

// ---------------------------------------------------------------------------
extern "C" void kernel_launch(void* const* d_in, const int* in_sizes, int n_in,
                              void* d_out, int out_size) {
    const int*   x = (const int*)d_in[0];   // [1, 8192] int32
    const float* p = (const float*)d_in[1]; // [8192, 16384] float32
    float* out = (float*)d_out;             // [1, 16384] float32

    dim3 grid(COL_TILES, ROW_STRIPS);
    k_gemv<<<grid, GEMV_TB>>>(x, p);
    k_topk<<<1, TK_THREADS>>>(out);
}

// round 9
// speedup vs baseline: 1.0776x; 1.0776x over previous
#include <cuda_runtime.h>

#define IN_DIM   8192
#define OUT_DIM  16384
#define TOP_K    327

// scratch (no allocations allowed); zero-initialized at module load, and
// k_topk re-zeroes it at the end of every launch (graph-replay invariant).
__device__ int g_overlap[OUT_DIM];

// ---------------------------------------------------------------------------
// k_gemv: overlap[c] += sum over active rows of (p[row][c] > 0.5f)
//   grid = (16 col tiles, 64 row strips), 256 threads. Ballot-compacts its
//   own 128-row strip of x, streams active rows' float4 column slices.
//   Measured at ~5.9 TB/s — at the LTS bandwidth ceiling. Do not touch.
// ---------------------------------------------------------------------------
#define GEMV_TB     256
#define STRIP       128
#define ROW_STRIPS  (IN_DIM / STRIP)        // 64
#define COLS_BLK    (GEMV_TB * 4)           // 1024
#define COL_TILES   (OUT_DIM / COLS_BLK)    // 16

__global__ __launch_bounds__(GEMV_TB, 7) void k_gemv(const int* __restrict__ x,
                                                     const float* __restrict__ p) {
    __shared__ int srows[STRIP];
    __shared__ int s_wcnt[4];

    const int t    = threadIdx.x;
    const int lane = t & 31;
    const int w    = t >> 5;
    const int r0   = blockIdx.y * STRIP;

    int a = 0, myrow = 0;
    unsigned m = 0;
    if (w < 4) {
        myrow = r0 + t;
        a = (x[myrow] != 0);
        m = __ballot_sync(0xffffffffu, a);
        if (lane == 0) s_wcnt[w] = __popc(m);
    }
    __syncthreads();
    const int nr = s_wcnt[0] + s_wcnt[1] + s_wcnt[2] + s_wcnt[3];
    if (w < 4 && a) {
        int off = 0;
        #pragma unroll
        for (int i = 0; i < 4; i++) if (i < w) off += s_wcnt[i];
        int rank = __popc(m & ((1u << lane) - 1u));
        srows[off + rank] = myrow;
    }
    __syncthreads();
    if (nr == 0) return;

    const int col4 = blockIdx.x * (COLS_BLK / 4) + t;
    const float4* __restrict__ p4 = (const float4*)p;
    const long stride4 = OUT_DIM / 4;

    int c0 = 0, c1 = 0, c2 = 0, c3 = 0;

    int r = 0;
    #pragma unroll 1
    for (; r + 4 <= nr; r += 4) {
        #pragma unroll
        for (int u = 0; u < 4; u++) {
            const int row = srows[r + u];
            const float4 v = __ldg(&p4[(long)row * stride4 + col4]);
            c0 += (v.x > 0.5f);
            c1 += (v.y > 0.5f);
            c2 += (v.z > 0.5f);
            c3 += (v.w > 0.5f);
        }
    }
    for (; r < nr; r++) {
        const int row = srows[r];
        const float4 v = __ldg(&p4[(long)row * stride4 + col4]);
        c0 += (v.x > 0.5f);
        c1 += (v.y > 0.5f);
        c2 += (v.z > 0.5f);
        c3 += (v.w > 0.5f);
    }

    const int cbase = col4 * 4;
    atomicAdd(&g_overlap[cbase + 0], c0);
    atomicAdd(&g_overlap[cbase + 1], c1);
    atomicAdd(&g_overlap[cbase + 2], c2);
    atomicAdd(&g_overlap[cbase + 3], c3);
}

// ---------------------------------------------------------------------------
// k_topk: single block, 1024 threads. Two-level histogram select:
//   coarse: 32 warp-private histograms of 128 bins (width 64) -> shfl-reduce
//   -> warp-0 suffix scan locates bin B of the k-th largest value.
//   fine: exact 65-bin histogram inside bin B -> warp-0 suffix scan -> T, rem.
//   Then jax.lax.top_k tie-break (lowest index wins among == T).
//   ~8 block barriers total (vs 39 for the old binary search).
// ---------------------------------------------------------------------------
#define TK_THREADS 1024
#define SEG        (OUT_DIM / TK_THREADS)   // 16
#define NCOARSE    128
#define HSTRIDE    132                       // pad: copies land in distinct banks
#define NCOPIES    32

__global__ __launch_bounds__(TK_THREADS) void k_topk(float* __restrict__ out) {
    __shared__ int s_hist[NCOPIES * HSTRIDE]; // ~16.5 KB
    __shared__ int s_coarse[NCOARSE];
    __shared__ int s_fine[65];
    __shared__ int s_warp[32];
    __shared__ int s_res[4];                  // B, cumAbove, T, rem

    const int t    = threadIdx.x;
    const int lane = t & 31;
    const int wid  = t >> 5;
    const int base = t * SEG;

    // load my 16 contiguous overlap values (int4 vectorized)
    int ov[SEG];
    int4* g4 = (int4*)(g_overlap + base);
    #pragma unroll
    for (int j = 0; j < SEG / 4; j++) {
        int4 v = g4[j];
        ov[4 * j + 0] = v.x;
        ov[4 * j + 1] = v.y;
        ov[4 * j + 2] = v.z;
        ov[4 * j + 3] = v.w;
    }

    // zero histograms
    for (int i = t; i < NCOPIES * HSTRIDE; i += TK_THREADS) s_hist[i] = 0;
    if (t < 65) s_fine[t] = 0;
    __syncthreads();

    // 1) coarse histogram, warp-private copy (conflicts only intra-warp)
    {
        int* my = s_hist + wid * HSTRIDE;
        #pragma unroll
        for (int j = 0; j < SEG; j++) {
            int b = ov[j] >> 6;
            atomicAdd(&my[b > 127 ? 127 : b], 1);
        }
    }
    __syncthreads();

    // 2) reduce 32 copies: thread t -> bin t>>3, part t&7 sums 4 copies,
    //    then 8-lane shfl_xor reduce (groups are 8 consecutive lanes)
    {
        int b = t >> 3, part = t & 7;
        int s = 0;
        #pragma unroll
        for (int i = 0; i < 4; i++)
            s += s_hist[(part * 4 + i) * HSTRIDE + b];
        s += __shfl_xor_sync(0xffffffffu, s, 1);
        s += __shfl_xor_sync(0xffffffffu, s, 2);
        s += __shfl_xor_sync(0xffffffffu, s, 4);
        if (part == 0) s_coarse[b] = s;
    }
    __syncthreads();

    // 3) warp 0: suffix scan over 128 coarse bins (4 per lane), find bin B
    if (wid == 0) {
        const int b0 = lane * 4;
        int c0 = s_coarse[b0 + 0], c1 = s_coarse[b0 + 1];
        int c2 = s_coarse[b0 + 2], c3 = s_coarse[b0 + 3];
        int loc = c0 + c1 + c2 + c3;
        int suf = loc;
        #pragma unroll
        for (int off = 1; off < 32; off <<= 1) {
            int v = __shfl_down_sync(0xffffffffu, suf, off);
            if (lane + off < 32) suf += v;
        }
        int above = suf - loc;  // count in bins strictly above my top bin
        int B = -1, cum = 0;
        if (above < TOP_K && above + c3 >= TOP_K) { B = b0 + 3; cum = above; }
        above += c3;
        if (B < 0 && above < TOP_K && above + c2 >= TOP_K) { B = b0 + 2; cum = above; }
        above += c2;
        if (B < 0 && above < TOP_K && above + c1 >= TOP_K) { B = b0 + 1; cum = above; }
        above += c1;
        if (B < 0 && above < TOP_K && above + c0 >= TOP_K) { B = b0 + 0; cum = above; }
        if (B >= 0) { s_res[0] = B; s_res[1] = cum; }
    }
    __syncthreads();
    const int B        = s_res[0];
    const int cumAbove = s_res[1];

    // 4) fine histogram inside bin B (values fbase..fbase+flim-1)
    const int fbase = B << 6;
    const int flim  = (B == 127) ? 65 : 64;  // bin 127 also holds v==8192
    #pragma unroll
    for (int j = 0; j < SEG; j++) {
        unsigned d = (unsigned)(ov[j] - fbase);
        if (d < (unsigned)flim) atomicAdd(&s_fine[d], 1);
    }
    __syncthreads();

    // 5) warp 0: suffix scan over 65 fine entries -> exact T and rem
    if (wid == 0) {
        const int e0 = 2 * lane, e1 = 2 * lane + 1;
        int f0 = s_fine[e0];
        int f1 = s_fine[e1];
        int f2 = (lane == 31) ? s_fine[64] : 0;  // entry 64 ranked highest
        int loc = f0 + f1 + f2;
        int suf = loc;
        #pragma unroll
        for (int off = 1; off < 32; off <<= 1) {
            int v = __shfl_down_sync(0xffffffffu, suf, off);
            if (lane + off < 32) suf += v;
        }
        int above = cumAbove + (suf - loc);
        int T = -1, rem = 0;
        if (lane == 31) {
            if (above < TOP_K && above + f2 >= TOP_K) { T = fbase + 64; rem = TOP_K - above; }
            above += f2;
        }
        if (T < 0 && above < TOP_K && above + f1 >= TOP_K) { T = fbase + e1; rem = TOP_K - above; }
        above += f1;
        if (T < 0 && above < TOP_K && above + f0 >= TOP_K) { T = fbase + e0; rem = TOP_K - above; }
        if (T >= 0) { s_res[2] = T; s_res[3] = rem; }
    }
    __syncthreads();
    const int T   = s_res[2];
    const int rem = s_res[3];

    // 6) tie ranking: exclusive prefix of tie-counts in ascending index order
    int cnt = 0;
    #pragma unroll
    for (int j = 0; j < SEG; j++) cnt += (ov[j] == T);

    int inc = cnt;
    #pragma unroll
    for (int o = 1; o < 32; o <<= 1) {
        int n = __shfl_up_sync(0xffffffffu, inc, o);
        if (lane >= o) inc += n;
    }
    if (lane == 31) s_warp[wid] = inc;
    __syncthreads();
    if (wid == 0) {
        int tot = s_warp[lane];
        int v = tot;
        #pragma unroll
        for (int o = 1; o < 32; o <<= 1) {
            int n = __shfl_up_sync(0xffffffffu, v, o);
            if (lane >= o) v += n;
        }
        s_warp[lane] = v - tot;
    }
    __syncthreads();
    int run = s_warp[wid] + (inc - cnt);

    // 7) emit 0/1 output, float4 stores
    float4* o4 = (float4*)(out + base);
    #pragma unroll
    for (int j = 0; j < SEG / 4; j++) {
        float r[4];
        #pragma unroll
        for (int q = 0; q < 4; q++) {
            int v = ov[4 * j + q];
            float o;
            if (v > T) {
                o = 1.0f;
            } else if (v == T) {
                o = (run < rem) ? 1.0f : 0.0f;
                run++;
            } else {
                o = 0.0f;
            }
            r[q] = o;
        }
        o4[j] = make_float4(r[0], r[1], r[2], r[3]);
    }

    // reset accumulator for the next graph replay
    #pragma unroll
    for (int j = 0; j < SEG / 4; j++)
        g4[j] = make_int4(0, 0, 0, 0);
}

// ---------------------------------------------------------------------------
extern "C" void kernel_launch(void* const* d_in, const int* in_sizes, int n_in,
                              void* d_out, int out_size) {
    const int*   x = (const int*)d_in[0];   // [1, 8192] int32
    const float* p = (const float*)d_in[1]; // [8192, 16384] float32
    float* out = (float*)d_out;             // [1, 16384] float32

    dim3 grid(COL_TILES, ROW_STRIPS);
    k_gemv<<<grid, GEMV_TB>>>(x, p);
    k_topk<<<1, TK_THREADS>>>(out);
}